// round 1
// baseline (speedup 1.0000x reference)
#include <cuda_runtime.h>
#include <cstdint>
#include <cstddef>

// Problem constants (fixed by the dataset): B=8, T=2048, D=1024, KQ=128, topk=8
#define Bz   8
#define Tz   2048
#define Dz   1024
#define KQz  128
#define TOPK 8
#define BT   (Bz * Tz)          // 16384 rows
#define SIM_SCALE 0.08838834764831843f   // 1/sqrt(128)

// Scratch (device globals: no allocation allowed in kernel_launch)
__device__ float g_q[BT * KQz];      // 8 MB
__device__ float g_k[BT * KQz];      // 8 MB
__device__ int   g_idx[BT * TOPK];   // routed indices (int form for gather)

// ---------------------------------------------------------------------------
// f32x2 packed-FMA helpers (Blackwell FFMA2: 2 fp32 FMA per instruction)
// ---------------------------------------------------------------------------
__device__ __forceinline__ unsigned long long pack2(float a, float b) {
    unsigned long long r;
    asm("mov.b64 %0, {%1, %2};" : "=l"(r)
        : "r"(__float_as_uint(a)), "r"(__float_as_uint(b)));
    return r;
}
__device__ __forceinline__ void unpack2(unsigned long long v, float& a, float& b) {
    unsigned int lo, hi;
    asm("mov.b64 {%0, %1}, %2;" : "=r"(lo), "=r"(hi) : "l"(v));
    a = __uint_as_float(lo);
    b = __uint_as_float(hi);
}
__device__ __forceinline__ void fma2(unsigned long long& d,
                                     unsigned long long a, unsigned long long b) {
    asm("fma.rn.f32x2 %0, %1, %2, %0;" : "+l"(d) : "l"(a), "l"(b));
}

__device__ __forceinline__ float neg_inf() { return __int_as_float(0xff800000); }

// ---------------------------------------------------------------------------
// Kernel 1: Q = x @ Wq^T + bq,  K = x @ Wk^T + bk      ([16384,1024]x[1024,128])
// CTA: 64 rows x 128 cols (both Q and K), BK=32, 256 threads, thread tile 4x8.
// ---------------------------------------------------------------------------
__global__ __launch_bounds__(256)
void qk_kernel(const float* __restrict__ x,
               const float* __restrict__ Wq, const float* __restrict__ bq,
               const float* __restrict__ Wk, const float* __restrict__ bk) {
    __shared__ float xs [32][68];    // [k][row], padded
    __shared__ float wqs[32][132];   // [k][col], padded (132 % 4 == 0 for float4)
    __shared__ float wks[32][132];

    const int tid = threadIdx.x;
    const int tx  = tid & 15;        // col group: 8 cols
    const int ty  = tid >> 4;        // row group: 4 rows
    const int rowstart = blockIdx.x * 64;
    const int col = tx * 8;

    unsigned long long accq[4][4], acck[4][4];
#pragma unroll
    for (int i = 0; i < 4; i++)
#pragma unroll
        for (int j = 0; j < 4; j++) { accq[i][j] = 0ull; acck[i][j] = 0ull; }

    for (int kb = 0; kb < 32; kb++) {
        // load x tile [64 rows x 32 k] transposed
#pragma unroll
        for (int i = 0; i < 2; i++) {
            int s = tid + i * 256;
            int r = s >> 3, c4 = s & 7;
            float4 v = *(const float4*)&x[(size_t)(rowstart + r) * Dz + kb * 32 + c4 * 4];
            xs[c4 * 4 + 0][r] = v.x; xs[c4 * 4 + 1][r] = v.y;
            xs[c4 * 4 + 2][r] = v.z; xs[c4 * 4 + 3][r] = v.w;
        }
        // load Wq/Wk tiles [128 cols x 32 k] transposed
#pragma unroll
        for (int i = 0; i < 4; i++) {
            int s = tid + i * 256;
            int n = s >> 3, c4 = s & 7;
            float4 v = *(const float4*)&Wq[(size_t)n * Dz + kb * 32 + c4 * 4];
            wqs[c4 * 4 + 0][n] = v.x; wqs[c4 * 4 + 1][n] = v.y;
            wqs[c4 * 4 + 2][n] = v.z; wqs[c4 * 4 + 3][n] = v.w;
            float4 w = *(const float4*)&Wk[(size_t)n * Dz + kb * 32 + c4 * 4];
            wks[c4 * 4 + 0][n] = w.x; wks[c4 * 4 + 1][n] = w.y;
            wks[c4 * 4 + 2][n] = w.z; wks[c4 * 4 + 3][n] = w.w;
        }
        __syncthreads();

#pragma unroll 8
        for (int kk = 0; kk < 32; kk++) {
            float4 a = *(const float4*)&xs[kk][ty * 4];
            unsigned long long ap0 = pack2(a.x, a.x), ap1 = pack2(a.y, a.y);
            unsigned long long ap2 = pack2(a.z, a.z), ap3 = pack2(a.w, a.w);

            float4 q0 = *(const float4*)&wqs[kk][col];
            float4 q1 = *(const float4*)&wqs[kk][col + 4];
            float4 k0 = *(const float4*)&wks[kk][col];
            float4 k1 = *(const float4*)&wks[kk][col + 4];
            unsigned long long bqp[4] = { pack2(q0.x, q0.y), pack2(q0.z, q0.w),
                                          pack2(q1.x, q1.y), pack2(q1.z, q1.w) };
            unsigned long long bkp[4] = { pack2(k0.x, k0.y), pack2(k0.z, k0.w),
                                          pack2(k1.x, k1.y), pack2(k1.z, k1.w) };
#pragma unroll
            for (int j = 0; j < 4; j++) {
                fma2(accq[0][j], ap0, bqp[j]); fma2(acck[0][j], ap0, bkp[j]);
                fma2(accq[1][j], ap1, bqp[j]); fma2(acck[1][j], ap1, bkp[j]);
                fma2(accq[2][j], ap2, bqp[j]); fma2(acck[2][j], ap2, bkp[j]);
                fma2(accq[3][j], ap3, bqp[j]); fma2(acck[3][j], ap3, bkp[j]);
            }
        }
        __syncthreads();
    }

    // epilogue: add bias, store
    float bqv[8], bkv[8];
#pragma unroll
    for (int j = 0; j < 8; j++) { bqv[j] = bq[col + j]; bkv[j] = bk[col + j]; }

#pragma unroll
    for (int i = 0; i < 4; i++) {
        float qv[8], kv[8];
#pragma unroll
        for (int j = 0; j < 4; j++) {
            unpack2(accq[i][j], qv[2 * j], qv[2 * j + 1]);
            unpack2(acck[i][j], kv[2 * j], kv[2 * j + 1]);
        }
        int grow = rowstart + ty * 4 + i;
        float4 o0 = { qv[0] + bqv[0], qv[1] + bqv[1], qv[2] + bqv[2], qv[3] + bqv[3] };
        float4 o1 = { qv[4] + bqv[4], qv[5] + bqv[5], qv[6] + bqv[6], qv[7] + bqv[7] };
        *(float4*)&g_q[(size_t)grow * KQz + col]     = o0;
        *(float4*)&g_q[(size_t)grow * KQz + col + 4] = o1;
        float4 p0 = { kv[0] + bkv[0], kv[1] + bkv[1], kv[2] + bkv[2], kv[3] + bkv[3] };
        float4 p1 = { kv[4] + bkv[4], kv[5] + bkv[5], kv[6] + bkv[6], kv[7] + bkv[7] };
        *(float4*)&g_k[(size_t)grow * KQz + col]     = p0;
        *(float4*)&g_k[(size_t)grow * KQz + col + 4] = p1;
    }
}

// ---------------------------------------------------------------------------
// top-8 insertion (register-resident, sorted desc, stable: lower index first)
// ---------------------------------------------------------------------------
__device__ __forceinline__ void topk_insert(float v, int i,
                                            float (&tv)[8], int (&ti)[8]) {
    if (v > tv[7]) {
        float pv = v; int pi = i;
#pragma unroll
        for (int p = 0; p < 8; p++) {
            if (pv > tv[p]) {
                float t = tv[p]; int u = ti[p];
                tv[p] = pv; ti[p] = pi;
                pv = t; pi = u;
            }
        }
    }
}

// Merge 16 lanes' sorted top-8 lists into a global top-8 for one row.
// Lanes 0..15 / 16..31 of a warp form independent groups (xor offsets <= 8).
__device__ __forceinline__ void merge_write(float (&tv)[8], int (&ti)[8],
                                            int grow, bool leader,
                                            float* __restrict__ out_idx,
                                            float* __restrict__ out_sim) {
    for (int r = 0; r < 8; r++) {
        float v = tv[0]; int i = ti[0];
#pragma unroll
        for (int off = 8; off >= 1; off >>= 1) {
            float ov = __shfl_xor_sync(0xffffffffu, v, off);
            int   oi = __shfl_xor_sync(0xffffffffu, i, off);
            if (ov > v || (ov == v && oi < i)) { v = ov; i = oi; }
        }
        if (ti[0] == i) {   // this lane's head won: pop it (static shift -> stays in regs)
#pragma unroll
            for (int p = 0; p < 7; p++) { tv[p] = tv[p + 1]; ti[p] = ti[p + 1]; }
            tv[7] = neg_inf(); ti[7] = 0x7fffffff;
        }
        if (leader) {
            out_idx[(size_t)grow * TOPK + r] = (float)i;
            out_sim[(size_t)grow * TOPK + r] = v;
            g_idx [(size_t)grow * TOPK + r] = i;
        }
    }
}

// ---------------------------------------------------------------------------
// Kernel 2: sim = (Q @ K^T) * scale, fused streaming top-8 per query row.
// CTA: 32 query rows x all 2048 keys (16 chunks of 128 keys). 256 threads.
// Thread tile: 2 rows x 8 keys. Lane tx in [0,16) covers keys == tx*8 (mod 128).
// ---------------------------------------------------------------------------
__global__ __launch_bounds__(256)
void sim_topk_kernel(float* __restrict__ out_idx, float* __restrict__ out_sim) {
    extern __shared__ float sm[];
    float* Qs = sm;                  // [128][36]  (d-major, padded)
    float* Ks = sm + 128 * 36;       // [128][132] (d-major, padded, 132%4==0)

    const int tid = threadIdx.x;
    const int tx  = tid & 15;
    const int ty  = tid >> 4;
    const int rowstart = blockIdx.x * 32;       // global query row base
    const int b = rowstart >> 11;               // / 2048
    const int keyoff = b * Tz;

    // load Q tile [32 rows x 128 d] transposed
#pragma unroll
    for (int i = 0; i < 4; i++) {
        int s = tid + i * 256;
        int r = s >> 5, c4 = s & 31;
        float4 v = *(const float4*)&g_q[(size_t)(rowstart + r) * KQz + c4 * 4];
        Qs[(c4 * 4 + 0) * 36 + r] = v.x; Qs[(c4 * 4 + 1) * 36 + r] = v.y;
        Qs[(c4 * 4 + 2) * 36 + r] = v.z; Qs[(c4 * 4 + 3) * 36 + r] = v.w;
    }

    float tv0[8], tv1[8]; int ti0[8], ti1[8];
#pragma unroll
    for (int p = 0; p < 8; p++) {
        tv0[p] = neg_inf(); tv1[p] = neg_inf();
        ti0[p] = 0x7fffffff; ti1[p] = 0x7fffffff;
    }

    for (int kb = 0; kb < 16; kb++) {
        __syncthreads();   // previous chunk's compute done (also covers Qs on kb==0)
        // load K chunk [128 keys x 128 d] transposed
#pragma unroll
        for (int i = 0; i < 16; i++) {
            int s = tid + i * 256;
            int t = s >> 5, c4 = s & 31;
            float4 v = *(const float4*)&g_k[(size_t)(keyoff + kb * 128 + t) * KQz + c4 * 4];
            Ks[(c4 * 4 + 0) * 132 + t] = v.x; Ks[(c4 * 4 + 1) * 132 + t] = v.y;
            Ks[(c4 * 4 + 2) * 132 + t] = v.z; Ks[(c4 * 4 + 3) * 132 + t] = v.w;
        }
        __syncthreads();

        unsigned long long accA[4] = {0ull, 0ull, 0ull, 0ull};
        unsigned long long accB[4] = {0ull, 0ull, 0ull, 0ull};
#pragma unroll 8
        for (int d = 0; d < 128; d++) {
            float2 a = *(const float2*)&Qs[d * 36 + ty * 2];
            unsigned long long ap0 = pack2(a.x, a.x);
            unsigned long long ap1 = pack2(a.y, a.y);
            float4 b0 = *(const float4*)&Ks[d * 132 + tx * 8];
            float4 b1 = *(const float4*)&Ks[d * 132 + tx * 8 + 4];
            unsigned long long bp[4] = { pack2(b0.x, b0.y), pack2(b0.z, b0.w),
                                         pack2(b1.x, b1.y), pack2(b1.z, b1.w) };
#pragma unroll
            for (int j = 0; j < 4; j++) {
                fma2(accA[j], ap0, bp[j]);
                fma2(accB[j], ap1, bp[j]);
            }
        }

        // feed scaled sims into running top-8 (ascending key index -> stable ties)
        int kbase = kb * 128 + tx * 8;
#pragma unroll
        for (int j = 0; j < 4; j++) {
            float v0, v1, w0, w1;
            unpack2(accA[j], v0, v1);
            unpack2(accB[j], w0, w1);
            topk_insert(v0 * SIM_SCALE, kbase + 2 * j,     tv0, ti0);
            topk_insert(v1 * SIM_SCALE, kbase + 2 * j + 1, tv0, ti0);
            topk_insert(w0 * SIM_SCALE, kbase + 2 * j,     tv1, ti1);
            topk_insert(w1 * SIM_SCALE, kbase + 2 * j + 1, tv1, ti1);
        }
    }

    // merge across the 16 lanes of each row group; leader lane writes results
    bool leader = (tx == 0);
    merge_write(tv0, ti0, rowstart + ty * 2,     leader, out_idx, out_sim);
    merge_write(tv1, ti1, rowstart + ty * 2 + 1, leader, out_idx, out_sim);
}

// ---------------------------------------------------------------------------
// Kernel 3: gather routed source-token embeddings. One CTA per (row, pick).
// ---------------------------------------------------------------------------
__global__ __launch_bounds__(128)
void gather_kernel(const float* __restrict__ x, float* __restrict__ out) {
    const int job = blockIdx.x;          // [0, BT*8)
    const int row = job >> 3;
    const int b   = row >> 11;           // / 2048
    const int idx = g_idx[job];
    const float* src = x + (size_t)(b * Tz + idx) * Dz;
    float* dst = out + (size_t)job * Dz;
    const int t = threadIdx.x;
    *(float4*)&dst[t * 4]       = *(const float4*)&src[t * 4];
    *(float4*)&dst[512 + t * 4] = *(const float4*)&src[512 + t * 4];
}

// ---------------------------------------------------------------------------
extern "C" void kernel_launch(void* const* d_in, const int* in_sizes, int n_in,
                              void* d_out, int out_size) {
    const float* x  = (const float*)d_in[0];
    const float* Wq = (const float*)d_in[1];
    const float* bq = (const float*)d_in[2];
    const float* Wk = (const float*)d_in[3];
    const float* bk = (const float*)d_in[4];

    float* out      = (float*)d_out;
    float* out_g    = out;                                   // [B,T,8,D]
    float* out_idx  = out + (size_t)BT * TOPK * Dz;          // [B,T,8] as float
    float* out_sim  = out_idx + (size_t)BT * TOPK;           // [B,T,8]

    const int smem2 = (128 * 36 + 128 * 132) * (int)sizeof(float);  // 86016
    cudaFuncSetAttribute(sim_topk_kernel,
                         cudaFuncAttributeMaxDynamicSharedMemorySize, smem2);

    qk_kernel<<<BT / 64, 256>>>(x, Wq, bq, Wk, bk);
    sim_topk_kernel<<<BT / 32, 256, smem2>>>(out_idx, out_sim);
    gather_kernel<<<BT * TOPK, 128>>>(x, out_g);
}

// round 2
// speedup vs baseline: 1.9707x; 1.9707x over previous
#include <cuda_runtime.h>
#include <cstdint>
#include <cstddef>

// Problem constants: B=8, T=2048, D=1024, KQ=128, topk=8
#define Bz   8
#define Tz   2048
#define Dz   1024
#define KQz  128
#define TOPK 8
#define BT   (Bz * Tz)          // 16384 rows
#define SIM_SCALE 0.08838834764831843f   // 1/sqrt(128)

typedef unsigned long long ull;

// Scratch (device globals: no allocation allowed in kernel_launch)
__device__ float g_q[BT * KQz];      // 8 MB
__device__ float g_k[BT * KQz];      // 8 MB
__device__ int   g_idx[BT * TOPK];   // routed indices for gather

// ---------------------------------------------------------------------------
// f32x2 packed-FMA helpers (FFMA2: 2 fp32 FMAs per instruction)
// ---------------------------------------------------------------------------
__device__ __forceinline__ ull pack2(float a, float b) {
    ull r;
    asm("mov.b64 %0, {%1, %2};" : "=l"(r)
        : "r"(__float_as_uint(a)), "r"(__float_as_uint(b)));
    return r;
}
__device__ __forceinline__ void unpack2(ull v, float& a, float& b) {
    unsigned int lo, hi;
    asm("mov.b64 {%0, %1}, %2;" : "=r"(lo), "=r"(hi) : "l"(v));
    a = __uint_as_float(lo);
    b = __uint_as_float(hi);
}
__device__ __forceinline__ void fma2(ull& d, ull a, ull b) {
    asm("fma.rn.f32x2 %0, %1, %2, %0;" : "+l"(d) : "l"(a), "l"(b));
}
__device__ __forceinline__ float neg_inf() { return __int_as_float(0xff800000); }

// ---------------------------------------------------------------------------
// Kernel 1: projection GEMM. blockIdx.y = 0 -> Q (Wq,bq), 1 -> K (Wk,bk).
// CTA tile 128 rows x 128 cols, 256 threads, 8x8 per thread, BK=32.
// Conflict-free transposed STS; register prefetch of next k-block.
// ---------------------------------------------------------------------------
__global__ __launch_bounds__(256)
void qk2_kernel(const float* __restrict__ x,
                const float* __restrict__ Wq, const float* __restrict__ bq,
                const float* __restrict__ Wk, const float* __restrict__ bk) {
    __shared__ float xs[32 * 132];   // [k][row], stride 132
    __shared__ float ws[32 * 132];   // [k][col], stride 132

    const float* W    = blockIdx.y ? Wk : Wq;
    const float* bias = blockIdx.y ? bk : bq;
    float* outp       = blockIdx.y ? g_k : g_q;

    const int tid  = threadIdx.x;
    const int tx   = tid & 15;          // 8 cols each  -> 128 cols
    const int ty   = tid >> 4;          // 8 rows each  -> 128 rows
    const int row0 = blockIdx.x * 128;

    // Loader index decomposition: s in [0,1024), warp = 16 rows x 2 f4-groups
    int c4a[4], ra[4];
#pragma unroll
    for (int i = 0; i < 4; i++) {
        int s = tid + i * 256;
        c4a[i] = (s & 1) + (((s >> 5) & 3) << 1);     // f4 index in k: [0,8)
        ra[i]  = ((s >> 1) & 15) + ((s >> 7) << 4);   // row/col: [0,128)
    }

    ull acc[8][4];
#pragma unroll
    for (int i = 0; i < 8; i++)
#pragma unroll
        for (int j = 0; j < 4; j++) acc[i][j] = 0ull;

    float4 px[4], pw[4];
    // prefetch k-block 0
#pragma unroll
    for (int i = 0; i < 4; i++) {
        px[i] = *(const float4*)&x[(size_t)(row0 + ra[i]) * Dz + c4a[i] * 4];
        pw[i] = *(const float4*)&W[(size_t)ra[i] * Dz + c4a[i] * 4];
    }

    for (int kb = 0; kb < 32; kb++) {
        // store prefetched block (conflict-free transpose)
#pragma unroll
        for (int i = 0; i < 4; i++) {
            int kbase = c4a[i] * 4, r = ra[i];
            xs[(kbase + 0) * 132 + r] = px[i].x; xs[(kbase + 1) * 132 + r] = px[i].y;
            xs[(kbase + 2) * 132 + r] = px[i].z; xs[(kbase + 3) * 132 + r] = px[i].w;
            ws[(kbase + 0) * 132 + r] = pw[i].x; ws[(kbase + 1) * 132 + r] = pw[i].y;
            ws[(kbase + 2) * 132 + r] = pw[i].z; ws[(kbase + 3) * 132 + r] = pw[i].w;
        }
        __syncthreads();

        if (kb < 31) {
            int koff = (kb + 1) * 32;
#pragma unroll
            for (int i = 0; i < 4; i++) {
                px[i] = *(const float4*)&x[(size_t)(row0 + ra[i]) * Dz + koff + c4a[i] * 4];
                pw[i] = *(const float4*)&W[(size_t)ra[i] * Dz + koff + c4a[i] * 4];
            }
        }

#pragma unroll 8
        for (int kk = 0; kk < 32; kk++) {
            float4 a0 = *(const float4*)&xs[kk * 132 + ty * 8];
            float4 a1 = *(const float4*)&xs[kk * 132 + ty * 8 + 4];
            ull ap[8] = { pack2(a0.x, a0.x), pack2(a0.y, a0.y),
                          pack2(a0.z, a0.z), pack2(a0.w, a0.w),
                          pack2(a1.x, a1.x), pack2(a1.y, a1.y),
                          pack2(a1.z, a1.z), pack2(a1.w, a1.w) };
            ulonglong2 b0 = *(const ulonglong2*)&ws[kk * 132 + tx * 8];
            ulonglong2 b1 = *(const ulonglong2*)&ws[kk * 132 + tx * 8 + 4];
            ull bp[4] = { b0.x, b0.y, b1.x, b1.y };
#pragma unroll
            for (int i = 0; i < 8; i++)
#pragma unroll
                for (int j = 0; j < 4; j++) fma2(acc[i][j], ap[i], bp[j]);
        }
        __syncthreads();
    }

    float bv[8];
#pragma unroll
    for (int j = 0; j < 8; j++) bv[j] = bias[tx * 8 + j];

#pragma unroll
    for (int i = 0; i < 8; i++) {
        float o[8];
#pragma unroll
        for (int j = 0; j < 4; j++) unpack2(acc[i][j], o[2 * j], o[2 * j + 1]);
        int grow = row0 + ty * 8 + i;
        float4 s0 = { o[0] + bv[0], o[1] + bv[1], o[2] + bv[2], o[3] + bv[3] };
        float4 s1 = { o[4] + bv[4], o[5] + bv[5], o[6] + bv[6], o[7] + bv[7] };
        *(float4*)&outp[(size_t)grow * KQz + tx * 8]     = s0;
        *(float4*)&outp[(size_t)grow * KQz + tx * 8 + 4] = s1;
    }
}

// ---------------------------------------------------------------------------
// top-8 insertion (sorted desc, stable: earlier index kept first on ties)
// ---------------------------------------------------------------------------
__device__ __forceinline__ void topk_insert(float v, int i,
                                            float (&tv)[8], int (&ti)[8]) {
    if (v > tv[7]) {
        float pv = v; int pi = i;
#pragma unroll
        for (int p = 0; p < 8; p++) {
            if (pv > tv[p]) {
                float t = tv[p]; int u = ti[p];
                tv[p] = pv; ti[p] = pi;
                pv = t; pi = u;
            }
        }
    }
}

// ---------------------------------------------------------------------------
// Kernel 2: sim = (Q @ K^T) * scale, fused streaming top-8.
// CTA: 64 query rows x 128-key chunks (16 chunks). 128 threads, 8x8 tiles.
// Per chunk: GEMM -> stage scaled tile into smem (overlay K buf) -> 2 threads
// per row scan halves into per-thread top-8 -> final xor-1 shuffle merge.
// ---------------------------------------------------------------------------
__global__ __launch_bounds__(128)
void sim_topk_kernel(float* __restrict__ out_idx, float* __restrict__ out_sim) {
    extern __shared__ float sm[];
    float* Qs = sm;             // [128 d][68]  (64 rows + pad)
    float* Ks = sm + 128 * 68;  // [128 d][132] (128 keys + pad); reused as Ss[64][132]

    const int tid  = threadIdx.x;
    const int tx   = tid & 15;        // 8 keys each  -> 128 keys
    const int ty   = tid >> 4;        // 8 rows each  -> 64 rows
    const int row0 = blockIdx.x * 64;
    const int b    = row0 >> 11;
    const int key0 = b * Tz;

    // load Q tile [64 rows x 128 d] transposed, conflict-free
#pragma unroll
    for (int i = 0; i < 16; i++) {
        int s  = tid + i * 128;
        int c4 = (s & 1) + (((s >> 5) & 15) << 1);    // [0,32)
        int r  = ((s >> 1) & 15) + ((s >> 9) << 4);   // [0,64)
        float4 v = *(const float4*)&g_q[(size_t)(row0 + r) * KQz + c4 * 4];
        Qs[(c4 * 4 + 0) * 68 + r] = v.x; Qs[(c4 * 4 + 1) * 68 + r] = v.y;
        Qs[(c4 * 4 + 2) * 68 + r] = v.z; Qs[(c4 * 4 + 3) * 68 + r] = v.w;
    }

    float tv[8]; int ti[8];
#pragma unroll
    for (int p = 0; p < 8; p++) { tv[p] = neg_inf(); ti[p] = 0x7fffffff; }

    const int srow = tid >> 1;        // scan row [0,64)
    const int shalf = tid & 1;        // scan half: keys [h*64, h*64+64)

    for (int kb = 0; kb < 16; kb++) {
        // load K chunk [128 keys x 128 d] transposed, conflict-free
#pragma unroll
        for (int i = 0; i < 32; i++) {
            int s  = tid + i * 128;
            int c4 = (s & 1) + (((s >> 5) & 15) << 1);    // [0,32)
            int t  = ((s >> 1) & 15) + ((s >> 9) << 4);   // [0,128)
            float4 v = *(const float4*)&g_k[(size_t)(key0 + kb * 128 + t) * KQz + c4 * 4];
            Ks[(c4 * 4 + 0) * 132 + t] = v.x; Ks[(c4 * 4 + 1) * 132 + t] = v.y;
            Ks[(c4 * 4 + 2) * 132 + t] = v.z; Ks[(c4 * 4 + 3) * 132 + t] = v.w;
        }
        __syncthreads();

        ull acc[8][4];
#pragma unroll
        for (int i = 0; i < 8; i++)
#pragma unroll
            for (int j = 0; j < 4; j++) acc[i][j] = 0ull;

#pragma unroll 8
        for (int d = 0; d < 128; d++) {
            float4 a0 = *(const float4*)&Qs[d * 68 + ty * 8];
            float4 a1 = *(const float4*)&Qs[d * 68 + ty * 8 + 4];
            ull ap[8] = { pack2(a0.x, a0.x), pack2(a0.y, a0.y),
                          pack2(a0.z, a0.z), pack2(a0.w, a0.w),
                          pack2(a1.x, a1.x), pack2(a1.y, a1.y),
                          pack2(a1.z, a1.z), pack2(a1.w, a1.w) };
            ulonglong2 b0 = *(const ulonglong2*)&Ks[d * 132 + tx * 8];
            ulonglong2 b1 = *(const ulonglong2*)&Ks[d * 132 + tx * 8 + 4];
            ull bp[4] = { b0.x, b0.y, b1.x, b1.y };
#pragma unroll
            for (int i = 0; i < 8; i++)
#pragma unroll
                for (int j = 0; j < 4; j++) fma2(acc[i][j], ap[i], bp[j]);
        }
        __syncthreads();   // all reads of Ks done before overlay

        // stage scaled sim tile into Ss (= Ks region): Ss[row][key], stride 132
#pragma unroll
        for (int i = 0; i < 8; i++) {
            float o[8];
#pragma unroll
            for (int j = 0; j < 4; j++) unpack2(acc[i][j], o[2 * j], o[2 * j + 1]);
            int r = ty * 8 + i;
            float4 s0 = { o[0] * SIM_SCALE, o[1] * SIM_SCALE,
                          o[2] * SIM_SCALE, o[3] * SIM_SCALE };
            float4 s1 = { o[4] * SIM_SCALE, o[5] * SIM_SCALE,
                          o[6] * SIM_SCALE, o[7] * SIM_SCALE };
            *(float4*)&Ks[r * 132 + tx * 8]     = s0;
            *(float4*)&Ks[r * 132 + tx * 8 + 4] = s1;
        }
        __syncthreads();

        // scan: 2 threads per row, 64 keys each, ascending index (stable ties)
        {
            const float* sp = &Ks[srow * 132 + shalf * 64];
            int kbase = kb * 128 + shalf * 64;
#pragma unroll
            for (int q = 0; q < 16; q++) {
                float4 v = *(const float4*)&sp[q * 4];
                topk_insert(v.x, kbase + q * 4 + 0, tv, ti);
                topk_insert(v.y, kbase + q * 4 + 1, tv, ti);
                topk_insert(v.z, kbase + q * 4 + 2, tv, ti);
                topk_insert(v.w, kbase + q * 4 + 3, tv, ti);
            }
        }
        __syncthreads();   // scan done before next chunk overwrites Ks
    }

    // merge the two half-lists of each row (threads tid, tid^1 in same warp)
    const bool lead = (tid & 1) == 0;
    const int grow = row0 + srow;
    for (int r = 0; r < 8; r++) {
        float v = tv[0]; int i = ti[0];
        float ov = __shfl_xor_sync(0xffffffffu, v, 1);
        int   oi = __shfl_xor_sync(0xffffffffu, i, 1);
        bool take_other = (ov > v) || (ov == v && oi < i);
        float wv = take_other ? ov : v;
        int   wi = take_other ? oi : i;
        if (!take_other) {   // my head won: pop
#pragma unroll
            for (int p = 0; p < 7; p++) { tv[p] = tv[p + 1]; ti[p] = ti[p + 1]; }
            tv[7] = neg_inf(); ti[7] = 0x7fffffff;
        }
        if (lead) {
            out_idx[(size_t)grow * TOPK + r] = (float)wi;
            out_sim[(size_t)grow * TOPK + r] = wv;
            g_idx [(size_t)grow * TOPK + r] = wi;
        }
    }
}

// ---------------------------------------------------------------------------
// Kernel 3: gather routed tokens. One CTA per query row; warp w copies pick w.
// ---------------------------------------------------------------------------
__global__ __launch_bounds__(256)
void gather_kernel(const float* __restrict__ x, float* __restrict__ out) {
    const int row  = blockIdx.x;
    const int w    = threadIdx.x >> 5;
    const int lane = threadIdx.x & 31;
    const int job  = row * TOPK + w;
    const int b    = row >> 11;
    const int idx  = g_idx[job];
    const float4* src = (const float4*)(x + (size_t)(b * Tz + idx) * Dz);
    float4* dst = (float4*)(out + (size_t)job * Dz);
#pragma unroll
    for (int j = 0; j < 8; j++) dst[j * 32 + lane] = src[j * 32 + lane];
}

// ---------------------------------------------------------------------------
extern "C" void kernel_launch(void* const* d_in, const int* in_sizes, int n_in,
                              void* d_out, int out_size) {
    const float* x  = (const float*)d_in[0];
    const float* Wq = (const float*)d_in[1];
    const float* bq = (const float*)d_in[2];
    const float* Wk = (const float*)d_in[3];
    const float* bk = (const float*)d_in[4];

    float* out      = (float*)d_out;
    float* out_g    = out;                                   // [B,T,8,D]
    float* out_idx  = out + (size_t)BT * TOPK * Dz;          // [B,T,8] as float
    float* out_sim  = out_idx + (size_t)BT * TOPK;           // [B,T,8]

    const int smem2 = (128 * 68 + 128 * 132) * (int)sizeof(float);  // 102400
    cudaFuncSetAttribute(sim_topk_kernel,
                         cudaFuncAttributeMaxDynamicSharedMemorySize, smem2);

    qk2_kernel<<<dim3(BT / 128, 2), 256>>>(x, Wq, bq, Wk, bk);
    sim_topk_kernel<<<BT / 64, 128, smem2>>>(out_idx, out_sim);
    gather_kernel<<<BT, 256>>>(x, out_g);
}